// round 13
// baseline (speedup 1.0000x reference)
#include <cuda_runtime.h>
#include <stdint.h>
#include <math.h>

#define BATCH 32
#define SH 96
#define SW 128
#define BH 768
#define BW 1024
#define KTAPS 49
#define PAD 24
#define SSTRIDE 129          // padded smem row stride -> conflict-free column access
#define STRIPES 6
#define SROWS 16             // rows per stripe
#define LROWS 64             // SROWS + 2*PAD halo rows loaded
#define NTHR 256
#define LOG64 4.1588830833596715f
#define CHUNK 4              // small rows staged per TMA chunk
#define NCHUNK (SROWS / CHUNK)

__device__ float d_partial[BATCH * STRIPES];
__device__ int   d_cnt[BATCH];    // stripes arrived (reset by last-done CTA)
__device__ int   d_done[BATCH];   // write phases finished (reset by last-done CTA)

// grid (STRIPES, BATCH) = 192 CTAs (all resident at occupancy 2), 256 threads.
// Phase 1: separable blur of a 16-row stripe (outputs kept in smem).
// Phase 2: intra-batch sync via atomics, local LSE, 8x8 expansion via
//          double-buffered TMA bulk stores.
__global__ __launch_bounds__(NTHR, 2)
void fused_kernel(float* __restrict__ out,
                  const float* __restrict__ readout,
                  const float* __restrict__ centerbias,
                  const float* __restrict__ sf,
                  const int*   __restrict__ dsidx,
                  const float* __restrict__ sigmas,
                  const float* __restrict__ cbws,
                  const float* __restrict__ pss,
                  int n_ds)
{
    extern __shared__ float smem[];
    float* s_in   = smem;                            // 8256 fl; reused as staging
    float* s_tmp  = smem + LROWS * SSTRIDE;          // 2064 fl: vertical result
    float* s_out  = s_tmp + SROWS * SSTRIDE;         // 2064 fl: final small values
    float* s_kern = s_out + SROWS * SSTRIDE;         // 64 (49 used)
    float* s_red  = s_kern + 64;                     // 8 used
    float* s_scal = s_red + 16;                      // [0]=prio [1]=cbw [3]=lse

    const int stripe = blockIdx.x;
    const int b      = blockIdx.y;
    const int r0     = stripe * SROWS;
    const int tid    = threadIdx.x;
    const int wid    = tid >> 5;
    const int lane   = tid & 31;

    // ---- Prefetch centerbias gather (scattered DRAM latency overlaps everything)
    const int h_lr = tid & 15;                  // horizontal-task row (0..15)
    const int h_c0 = (tid >> 4) * 8;            // horizontal-task col group
    const float* cbp = centerbias + (size_t)b * BH * BW
                     + (size_t)((r0 + h_lr) * 8) * BW;
    float cbv[8];
    #pragma unroll
    for (int j = 0; j < 8; j++) cbv[j] = __ldg(&cbp[(h_c0 + j) * 8]);

    // ---- Readout tile -> smem via cp.async (no registers, latency overlapped).
    const float* rp = readout + b * SH * SW;
    {
        unsigned int sbase;
        asm("{ .reg .u64 t; cvta.to.shared.u64 t, %1; cvt.u32.u64 %0, t; }"
            : "=r"(sbase) : "l"(s_in));
        #pragma unroll
        for (int j = 0; j < LROWS * SW / NTHR; j++) {      // 32 per thread
            int i  = tid + j * NTHR;
            int jr = i >> 7;
            int g  = r0 - PAD + jr;
            g = g < 0 ? 0 : (g > SH - 1 ? SH - 1 : g);
            unsigned int sa = sbase + (jr * SSTRIDE + (i & 127)) * 4;
            const float* ga = rp + g * SW + (i & 127);
            asm volatile("cp.async.ca.shared.global [%0], [%1], 4;"
                         :: "r"(sa), "l"(ga));
        }
        asm volatile("cp.async.commit_group;" ::: "memory");
    }

    // kernel taps + scalars (overlap cp.async in flight)
    if (tid < KTAPS) {
        int di = dsidx[b];
        float sigma = sigmas[di] * sf[b];
        float inv2s2 = 0.5f / (sigma * sigma);
        float d = (float)(tid - PAD);
        s_kern[tid] = expf(-d * d * inv2s2);
        if (tid == 0) {
            float m = 0.f;
            for (int j = 0; j < n_ds; j++) m += pss[j];
            m /= (float)n_ds;
            s_scal[0] = expf(pss[di] - m);
            s_scal[1] = cbws[di];
        }
    }
    __syncthreads();
    if (tid == 0) {       // normalize taps in place (both passes use them)
        float s = 0.f;
        for (int k = 0; k < KTAPS; k++) s += s_kern[k];
        float inv = 1.f / s;
        for (int k = 0; k < KTAPS; k++) s_kern[k] *= inv;
    }
    asm volatile("cp.async.wait_group 0;" ::: "memory");
    __syncthreads();

    // ---- Vertical pass (halo in smem, no clamping). 256 tasks = 1/thread.
    {
        int col = tid & 127;
        int lr0 = (tid >> 7) * 8;       // 0 or 8
        float w[8], acc[8];
        #pragma unroll
        for (int j = 0; j < 8; j++) {
            w[j] = s_in[(lr0 + j) * SSTRIDE + col];
            acc[j] = 0.f;
        }
        #pragma unroll
        for (int k = 0; k < KTAPS; k++) {
            float tap = s_kern[k];
            #pragma unroll
            for (int j = 0; j < 8; j++) acc[j] = fmaf(tap, w[j], acc[j]);
            if (k < KTAPS - 1) {
                #pragma unroll
                for (int j = 0; j < 7; j++) w[j] = w[j + 1];
                w[7] = s_in[(lr0 + k + 8) * SSTRIDE + col];
            }
        }
        #pragma unroll
        for (int j = 0; j < 8; j++) s_tmp[(lr0 + j) * SSTRIDE + col] = acc[j];
    }
    __syncthreads();

    // ---- Horizontal pass -> s_out (stays in smem).
    float prio = s_scal[0], cbw = s_scal[1];
    float lsum = 0.f;
    {
        const float* trow = s_tmp + h_lr * SSTRIDE;
        float w[8], acc[8];
        #pragma unroll
        for (int j = 0; j < 8; j++) {
            int cc = h_c0 - PAD + j;
            cc = cc < 0 ? 0 : cc;
            w[j] = trow[cc];
            acc[j] = 0.f;
        }
        #pragma unroll
        for (int k = 0; k < KTAPS; k++) {
            float tap = s_kern[k];
            #pragma unroll
            for (int j = 0; j < 8; j++) acc[j] = fmaf(tap, w[j], acc[j]);
            if (k < KTAPS - 1) {
                #pragma unroll
                for (int j = 0; j < 7; j++) w[j] = w[j + 1];
                int cc = h_c0 + k - 16;
                cc = cc < 0 ? 0 : (cc > SW - 1 ? SW - 1 : cc);
                w[7] = trow[cc];
            }
        }
        #pragma unroll
        for (int j = 0; j < 8; j++) {
            float v = prio * acc[j] + cbw * cbv[j];
            s_out[h_lr * SSTRIDE + h_c0 + j] = v;
            lsum += __expf(v);
        }
    }

    // ---- Publish stripe partial, spin for batch completion, compute LSE.
    #pragma unroll
    for (int o = 16; o > 0; o >>= 1) lsum += __shfl_xor_sync(0xFFFFFFFFu, lsum, o);
    if (lane == 0) s_red[wid] = lsum;
    __syncthreads();
    if (tid == 0) {
        float s = 0.f;
        for (int i = 0; i < NTHR / 32; i++) s += s_red[i];
        d_partial[b * STRIPES + stripe] = s;
        __threadfence();
        atomicAdd(&d_cnt[b], 1);
        volatile int* vc = &d_cnt[b];
        while (*vc < STRIPES) __nanosleep(100);
        __threadfence();
        float p = 0.f;
        #pragma unroll
        for (int i = 0; i < STRIPES; i++) p += d_partial[b * STRIPES + i];
        s_scal[3] = logf(p) + LOG64;
    }
    __syncthreads();
    const float lse = s_scal[3];

    // ---- Write phase: 16 small rows -> 128 big rows, double-buffered TMA.
    // Staging reuses s_in: two 4-row buffers (16 KB each), 8192 <= 8256 floats.
    for (int c = 0; c < NCHUNK; c++) {
        if (tid == 0)
            asm volatile("cp.async.bulk.wait_group 1;" ::: "memory"); // buf free
        __syncthreads();
        float* buf = s_in + (c & 1) * (CHUNK * BW);
        for (int i4 = tid; i4 < CHUNK * BW / 4; i4 += NTHR) {
            int row = i4 >> 8;            // /256 float4 per big row
            int ii  = i4 & 255;
            int sc  = ii >> 1;            // small col (each float4 is one sc half)
            float v = s_out[(c * CHUNK + row) * SSTRIDE + sc] - lse;
            ((float4*)buf)[i4] = make_float4(v, v, v, v);
        }
        __syncthreads();
        if (tid == 0) {
            asm volatile("fence.proxy.async.shared::cta;" ::: "memory");
            #pragma unroll
            for (int row = 0; row < CHUNK; row++) {
                unsigned int saddr;
                asm("{ .reg .u64 t; cvta.to.shared.u64 t, %1; cvt.u32.u64 %0, t; }"
                    : "=r"(saddr) : "l"(buf + row * BW));
                float* gbase = out + (size_t)b * BH * BW
                             + (size_t)((r0 + c * CHUNK + row) * 8) * BW;
                #pragma unroll
                for (int rep = 0; rep < 8; rep++) {
                    asm volatile(
                        "cp.async.bulk.global.shared::cta.bulk_group [%0], [%1], %2;"
                        :: "l"(gbase + (size_t)rep * BW), "r"(saddr), "n"(BW * 4)
                        : "memory");
                }
            }
            asm volatile("cp.async.bulk.commit_group;" ::: "memory");
        }
    }
    if (tid == 0)
        asm volatile("cp.async.bulk.wait_group 0;" ::: "memory");
    __syncthreads();

    // ---- Reset sync state for graph replay (last finisher per batch).
    if (tid == 0) {
        int old = atomicAdd(&d_done[b], 1);
        if (old == STRIPES - 1) {
            d_cnt[b]  = 0;
            d_done[b] = 0;
        }
    }
}

extern "C" void kernel_launch(void* const* d_in, const int* in_sizes, int n_in,
                              void* d_out, int out_size)
{
    const float* readout    = (const float*)d_in[0];
    const float* centerbias = (const float*)d_in[1];
    const float* sf         = (const float*)d_in[2];
    const int*   dsidx      = (const int*)  d_in[3];
    const float* sigmas     = (const float*)d_in[4];
    const float* cbws       = (const float*)d_in[5];
    const float* pss        = (const float*)d_in[6];
    int n_ds = in_sizes[4];

    const int smem_bytes =
        (LROWS * SSTRIDE + 2 * SROWS * SSTRIDE + 64 + 16 + 8) * (int)sizeof(float);
    cudaFuncSetAttribute(fused_kernel, cudaFuncAttributeMaxDynamicSharedMemorySize,
                         smem_bytes);

    fused_kernel<<<dim3(STRIPES, BATCH), NTHR, smem_bytes>>>(
        (float*)d_out, readout, centerbias, sf, dsidx, sigmas, cbws, pss, n_ds);
}

// round 14
// speedup vs baseline: 1.2044x; 1.2044x over previous
#include <cuda_runtime.h>
#include <stdint.h>
#include <math.h>

#define BATCH 32
#define SH 96
#define SW 128
#define BH 768
#define BW 1024
#define KTAPS 49
#define PAD 24
#define SSTRIDE 129          // padded smem row stride -> conflict-free column access
#define STRIPES 4
#define SROWS 24             // rows per stripe
#define LROWS 72             // SROWS + 2*PAD halo rows loaded
#define NTHR 768
#define LOG64 4.1588830833596715f
#define CHUNK 4              // small rows staged per TMA chunk
#define NCHUNK (SROWS / CHUNK)

__device__ float d_partial[BATCH * STRIPES];
__device__ int   d_cnt[BATCH];    // stripes arrived (reset by last-done CTA)
__device__ int   d_done[BATCH];   // write phases finished (reset by last-done CTA)

// grid (STRIPES, BATCH) = 128 CTAs (single wave, all resident), 768 threads.
// 4-wide tasks -> 24 warps/SM for the same total FMA work (latency hiding).
__global__ __launch_bounds__(NTHR, 1)
void fused_kernel(float* __restrict__ out,
                  const float* __restrict__ readout,
                  const float* __restrict__ centerbias,
                  const float* __restrict__ sf,
                  const int*   __restrict__ dsidx,
                  const float* __restrict__ sigmas,
                  const float* __restrict__ cbws,
                  const float* __restrict__ pss,
                  int n_ds)
{
    extern __shared__ float smem[];
    float* s_in   = smem;                            // 9288 fl; reused as staging
    float* s_tmp  = smem + LROWS * SSTRIDE;          // 3096 fl: vertical result
    float* s_out  = s_tmp + SROWS * SSTRIDE;         // 3096 fl: final small values
    float* s_kern = s_out + SROWS * SSTRIDE;         // 64 (49 used)
    float* s_red  = s_kern + 64;                     // 24 used
    float* s_scal = s_red + 32;                      // [0]=prio [1]=cbw [3]=lse

    const int stripe = blockIdx.x;
    const int b      = blockIdx.y;
    const int r0     = stripe * SROWS;
    const int tid    = threadIdx.x;
    const int wid    = tid >> 5;
    const int lane   = tid & 31;

    // ---- Prefetch centerbias gather (4 scattered values per thread).
    const int h_lr = tid % SROWS;               // horizontal-task row (0..23)
    const int h_c0 = (tid / SROWS) * 4;         // horizontal-task col group (x4)
    const float* cbp = centerbias + (size_t)b * BH * BW
                     + (size_t)((r0 + h_lr) * 8) * BW;
    float cbv[4];
    #pragma unroll
    for (int j = 0; j < 4; j++) cbv[j] = __ldg(&cbp[(h_c0 + j) * 8]);

    // ---- Readout tile into registers (12 independent LDGs), STS deferred.
    const float* rp = readout + b * SH * SW;
    float rin[12];
    #pragma unroll
    for (int j = 0; j < 12; j++) {
        int i  = tid + j * NTHR;
        int jr = i >> 7;
        int g  = r0 - PAD + jr;
        g = g < 0 ? 0 : (g > SH - 1 ? SH - 1 : g);
        rin[j] = __ldg(&rp[g * SW + (i & 127)]);
    }

    // kernel taps + scalars
    if (tid < KTAPS) {
        int di = dsidx[b];
        float sigma = sigmas[di] * sf[b];
        float inv2s2 = 0.5f / (sigma * sigma);
        float d = (float)(tid - PAD);
        s_kern[tid] = expf(-d * d * inv2s2);
        if (tid == 0) {
            float m = 0.f;
            for (int j = 0; j < n_ds; j++) m += pss[j];
            m /= (float)n_ds;
            s_scal[0] = expf(pss[di] - m);
            s_scal[1] = cbws[di];
        }
    }
    __syncthreads();
    if (tid == 0) {       // normalize taps in place (both passes use them)
        float s = 0.f;
        for (int k = 0; k < KTAPS; k++) s += s_kern[k];
        float inv = 1.f / s;
        for (int k = 0; k < KTAPS; k++) s_kern[k] *= inv;
    }
    #pragma unroll
    for (int j = 0; j < 12; j++) {
        int i = tid + j * NTHR;
        s_in[(i >> 7) * SSTRIDE + (i & 127)] = rin[j];
    }
    __syncthreads();

    // ---- Vertical pass: 768 tasks = 1/thread (col, 4-row group). No clamping.
    {
        int col = tid & 127;
        int lr0 = (tid >> 7) * 4;       // 0,4,8,12,16,20
        float w[4], acc[4];
        #pragma unroll
        for (int j = 0; j < 4; j++) {
            w[j] = s_in[(lr0 + j) * SSTRIDE + col];
            acc[j] = 0.f;
        }
        #pragma unroll
        for (int k = 0; k < KTAPS; k++) {
            float tap = s_kern[k];
            #pragma unroll
            for (int j = 0; j < 4; j++) acc[j] = fmaf(tap, w[j], acc[j]);
            if (k < KTAPS - 1) {
                #pragma unroll
                for (int j = 0; j < 3; j++) w[j] = w[j + 1];
                w[3] = s_in[(lr0 + k + 4) * SSTRIDE + col];
            }
        }
        #pragma unroll
        for (int j = 0; j < 4; j++) s_tmp[(lr0 + j) * SSTRIDE + col] = acc[j];
    }
    __syncthreads();

    // ---- Horizontal pass: 768 tasks = 1/thread (row h_lr, cols h_c0..+3).
    float prio = s_scal[0], cbw = s_scal[1];
    float lsum = 0.f;
    {
        const float* trow = s_tmp + h_lr * SSTRIDE;
        float w[4], acc[4];
        #pragma unroll
        for (int j = 0; j < 4; j++) {
            int cc = h_c0 - PAD + j;
            cc = cc < 0 ? 0 : cc;
            w[j] = trow[cc];
            acc[j] = 0.f;
        }
        #pragma unroll
        for (int k = 0; k < KTAPS; k++) {
            float tap = s_kern[k];
            #pragma unroll
            for (int j = 0; j < 4; j++) acc[j] = fmaf(tap, w[j], acc[j]);
            if (k < KTAPS - 1) {
                #pragma unroll
                for (int j = 0; j < 3; j++) w[j] = w[j + 1];
                int cc = h_c0 + k - 20;     // c0 - PAD + (k+1) + 3
                cc = cc < 0 ? 0 : (cc > SW - 1 ? SW - 1 : cc);
                w[3] = trow[cc];
            }
        }
        #pragma unroll
        for (int j = 0; j < 4; j++) {
            float v = prio * acc[j] + cbw * cbv[j];
            s_out[h_lr * SSTRIDE + h_c0 + j] = v;
            lsum += __expf(v);
        }
    }

    // ---- Publish stripe partial, spin for batch completion, compute LSE.
    #pragma unroll
    for (int o = 16; o > 0; o >>= 1) lsum += __shfl_xor_sync(0xFFFFFFFFu, lsum, o);
    if (lane == 0) s_red[wid] = lsum;
    __syncthreads();
    if (tid == 0) {
        float s = 0.f;
        for (int i = 0; i < NTHR / 32; i++) s += s_red[i];
        d_partial[b * STRIPES + stripe] = s;
        __threadfence();
        atomicAdd(&d_cnt[b], 1);
        volatile int* vc = &d_cnt[b];
        while (*vc < STRIPES) __nanosleep(100);
        __threadfence();
        float p = d_partial[b * STRIPES + 0] + d_partial[b * STRIPES + 1]
                + d_partial[b * STRIPES + 2] + d_partial[b * STRIPES + 3];
        s_scal[3] = logf(p) + LOG64;
    }
    __syncthreads();
    const float lse = s_scal[3];

    // ---- Write phase: 24 small rows -> 192 big rows, double-buffered TMA.
    for (int c = 0; c < NCHUNK; c++) {
        if (tid == 0)
            asm volatile("cp.async.bulk.wait_group 1;" ::: "memory"); // buf free
        __syncthreads();
        float* buf = s_in + (c & 1) * (CHUNK * BW);
        for (int i4 = tid; i4 < CHUNK * BW / 4; i4 += NTHR) {
            int row = i4 >> 8;            // /256 float4 per big row
            int ii  = i4 & 255;
            int sc  = ii >> 1;            // small col
            float v = s_out[(c * CHUNK + row) * SSTRIDE + sc] - lse;
            ((float4*)buf)[i4] = make_float4(v, v, v, v);
        }
        __syncthreads();
        if (tid == 0) {
            asm volatile("fence.proxy.async.shared::cta;" ::: "memory");
            #pragma unroll
            for (int row = 0; row < CHUNK; row++) {
                unsigned int saddr;
                asm("{ .reg .u64 t; cvta.to.shared.u64 t, %1; cvt.u32.u64 %0, t; }"
                    : "=r"(saddr) : "l"(buf + row * BW));
                float* gbase = out + (size_t)b * BH * BW
                             + (size_t)((r0 + c * CHUNK + row) * 8) * BW;
                #pragma unroll
                for (int rep = 0; rep < 8; rep++) {
                    asm volatile(
                        "cp.async.bulk.global.shared::cta.bulk_group [%0], [%1], %2;"
                        :: "l"(gbase + (size_t)rep * BW), "r"(saddr), "n"(BW * 4)
                        : "memory");
                }
            }
            asm volatile("cp.async.bulk.commit_group;" ::: "memory");
        }
    }
    if (tid == 0)
        asm volatile("cp.async.bulk.wait_group 0;" ::: "memory");
    __syncthreads();

    // ---- Reset sync state for graph replay (last finisher per batch).
    if (tid == 0) {
        int old = atomicAdd(&d_done[b], 1);
        if (old == STRIPES - 1) {
            d_cnt[b]  = 0;
            d_done[b] = 0;
        }
    }
}

extern "C" void kernel_launch(void* const* d_in, const int* in_sizes, int n_in,
                              void* d_out, int out_size)
{
    const float* readout    = (const float*)d_in[0];
    const float* centerbias = (const float*)d_in[1];
    const float* sf         = (const float*)d_in[2];
    const int*   dsidx      = (const int*)  d_in[3];
    const float* sigmas     = (const float*)d_in[4];
    const float* cbws       = (const float*)d_in[5];
    const float* pss        = (const float*)d_in[6];
    int n_ds = in_sizes[4];

    const int smem_bytes =
        (LROWS * SSTRIDE + 2 * SROWS * SSTRIDE + 64 + 32 + 8) * (int)sizeof(float);
    cudaFuncSetAttribute(fused_kernel, cudaFuncAttributeMaxDynamicSharedMemorySize,
                         smem_bytes);

    fused_kernel<<<dim3(STRIPES, BATCH), NTHR, smem_bytes>>>(
        (float*)d_out, readout, centerbias, sf, dsidx, sigmas, cbws, pss, n_ds);
}